// round 1
// baseline (speedup 1.0000x reference)
#include <cuda_runtime.h>
#include <stdint.h>

#define BATCH 16
#define SEQ   2048
#define HID   1024
#define VOCAB 250002
#define SM1   2047                 // S-1
#define MROWS (BATCH * SM1)        // 32752 colbert rows
#define EPSV  1e-12f

static const size_t OFF_SPARSE  = (size_t)BATCH * HID;                 // 16384
static const size_t OFF_COLBERT = OFF_SPARSE + (size_t)BATCH * VOCAB;  // 4016416

// Deterministic per-row sum-of-squares partials: [row][n_tile(8)]
__device__ float g_ssq_part[(size_t)MROWS * 8];
__device__ int   g_is64;

// ---------------------------------------------------------------------------
// Detect whether input_ids buffer is int64 or int32.
// If int64 (little-endian, ids < 2^31), every odd 32-bit word in the first
// B*S words is the zero hi-word. If int32, odd words are random vocab ids
// (~all nonzero). Scanning only the first B*S words is in-bounds for both.
// ---------------------------------------------------------------------------
__global__ void detect_i64_kernel(const unsigned int* __restrict__ w) {
    __shared__ int anynz;
    if (threadIdx.x == 0) anynz = 0;
    __syncthreads();
    int loc = 0;
    for (int i = threadIdx.x; i < BATCH * SEQ / 2; i += blockDim.x)
        loc |= (w[2 * i + 1] != 0u);
    if (loc) atomicOr(&anynz, 1);
    __syncthreads();
    if (threadIdx.x == 0) g_is64 = (anynz == 0);
}

// ---------------------------------------------------------------------------
// Dense: L2-normalize CLS token of each batch. 16 blocks x 256 threads.
// ---------------------------------------------------------------------------
__global__ void dense_kernel(const float* __restrict__ hs, float* __restrict__ out) {
    int b = blockIdx.x, t = threadIdx.x;
    const float4* x4 = (const float4*)(hs + (size_t)b * SEQ * HID);
    float4 v = x4[t];
    float s = v.x * v.x + v.y * v.y + v.z * v.z + v.w * v.w;
    #pragma unroll
    for (int o = 16; o; o >>= 1) s += __shfl_xor_sync(0xffffffffu, s, o);
    __shared__ float red[8];
    __shared__ float scv;
    if ((t & 31) == 0) red[t >> 5] = s;
    __syncthreads();
    if (t == 0) {
        float a = 0.f;
        #pragma unroll
        for (int i = 0; i < 8; i++) a += red[i];
        scv = 1.f / fmaxf(sqrtf(a), EPSV);
    }
    __syncthreads();
    float sc = scv;
    v.x *= sc; v.y *= sc; v.z *= sc; v.w *= sc;
    ((float4*)(out + (size_t)b * HID))[t] = v;
}

// ---------------------------------------------------------------------------
// Sparse: one warp per token. dot(hidden[b,s,:], sparse_W) + b, relu,
// scatter-max into (B, VOCAB). Skipping ids<4 == zeroing special tokens.
// Grid: 4096 blocks x 256 threads = 32768 warps = B*S exactly.
// ---------------------------------------------------------------------------
__global__ void sparse_kernel(const float* __restrict__ hs,
                              const float* __restrict__ sW,
                              const float* __restrict__ sb,
                              const void* __restrict__ ids,
                              float* __restrict__ sparse_out) {
    __shared__ float4 w4[HID / 4];
    for (int i = threadIdx.x; i < HID / 4; i += blockDim.x)
        w4[i] = ((const float4*)sW)[i];
    __syncthreads();

    int gw   = (blockIdx.x * blockDim.x + threadIdx.x) >> 5;  // token idx
    int lane = threadIdx.x & 31;
    const float4* x4 = (const float4*)(hs + (size_t)gw * HID);
    float s = 0.f;
    #pragma unroll
    for (int i = 0; i < 8; i++) {
        float4 a = x4[lane + i * 32];
        float4 b = w4[lane + i * 32];
        s += a.x * b.x + a.y * b.y + a.z * b.z + a.w * b.w;
    }
    #pragma unroll
    for (int o = 16; o; o >>= 1) s += __shfl_xor_sync(0xffffffffu, s, o);
    if (lane == 0) {
        float tw = s + sb[0];
        if (tw > 0.f) {
            long long id = g_is64 ? ((const long long*)ids)[gw]
                                  : (long long)((const int*)ids)[gw];
            if (id >= 4) {
                int b = gw / SEQ;
                atomicMax((unsigned int*)(sparse_out + (size_t)b * VOCAB + (size_t)id),
                          __float_as_uint(tw));  // valid: values >= 0
            }
        }
    }
}

// ---------------------------------------------------------------------------
// Colbert GEMM: C[m, n] = sum_h A[m, h] * W[h, n] + bias[n], then * mask.
// A row m maps to hidden row (m + m/SM1 + 1)  (skips token 0 of each batch).
// 128x128x16 tile, 8x8 per thread, 256 threads. Writes deterministic per-row
// sumsq partial for its N-tile into g_ssq_part.
// ---------------------------------------------------------------------------
__global__ __launch_bounds__(256, 2)
void colbert_gemm_kernel(const float* __restrict__ A,
                         const float* __restrict__ Wm,
                         const float* __restrict__ bias,
                         const float* __restrict__ amask,
                         float* __restrict__ Cout) {
    __shared__ float As[16][128];   // transposed A tile: As[k][m]
    __shared__ float Bs[16][128];   // Bs[k][n]

    const int tid = threadIdx.x;
    const int bx  = blockIdx.x;           // N tile (0..7)
    const int m0  = blockIdx.y * 128;     // M tile base
    const int n0  = bx * 128;

    const int tr = tid >> 4;              // 0..15 (row group of 8)
    const int tc = tid & 15;              // 0..15 (col group of 8)

    // A tile loads: 512 float4s -> thread covers v=tid and v=tid+256
    const int arow0 = tid >> 2;
    const int arow1 = arow0 + 64;
    const int acol  = (tid & 3) << 2;
    // B tile loads
    const int brow0 = tid >> 5;           // 0..7
    const int brow1 = brow0 + 8;
    const int bcol  = (tid & 31) << 2;

    const int  ma0 = m0 + arow0;
    const int  ma1 = m0 + arow1;
    const bool av0 = ma0 < MROWS;
    const bool av1 = ma1 < MROWS;
    const size_t ga0 = av0 ? (size_t)(ma0 + ma0 / SM1 + 1) * HID : 0;
    const size_t ga1 = av1 ? (size_t)(ma1 + ma1 / SM1 + 1) * HID : 0;

    float acc[8][8];
    #pragma unroll
    for (int i = 0; i < 8; i++)
        #pragma unroll
        for (int j = 0; j < 8; j++) acc[i][j] = 0.f;

    for (int k0 = 0; k0 < HID; k0 += 16) {
        float4 a0 = av0 ? *(const float4*)(A + ga0 + k0 + acol) : make_float4(0, 0, 0, 0);
        float4 a1 = av1 ? *(const float4*)(A + ga1 + k0 + acol) : make_float4(0, 0, 0, 0);
        float4 b0 = *(const float4*)(Wm + (size_t)(k0 + brow0) * HID + n0 + bcol);
        float4 b1 = *(const float4*)(Wm + (size_t)(k0 + brow1) * HID + n0 + bcol);

        if (k0) __syncthreads();  // previous iter's compute done before overwrite
        As[acol + 0][arow0] = a0.x; As[acol + 1][arow0] = a0.y;
        As[acol + 2][arow0] = a0.z; As[acol + 3][arow0] = a0.w;
        As[acol + 0][arow1] = a1.x; As[acol + 1][arow1] = a1.y;
        As[acol + 2][arow1] = a1.z; As[acol + 3][arow1] = a1.w;
        *(float4*)&Bs[brow0][bcol] = b0;
        *(float4*)&Bs[brow1][bcol] = b1;
        __syncthreads();

        #pragma unroll
        for (int k = 0; k < 16; k++) {
            float ra[8], rb[8];
            #pragma unroll
            for (int i = 0; i < 8; i++) ra[i] = As[k][tr * 8 + i];
            #pragma unroll
            for (int j = 0; j < 8; j++) rb[j] = Bs[k][tc * 8 + j];
            #pragma unroll
            for (int i = 0; i < 8; i++)
                #pragma unroll
                for (int j = 0; j < 8; j++)
                    acc[i][j] = fmaf(ra[i], rb[j], acc[i][j]);
        }
    }

    float bl[8];
    #pragma unroll
    for (int j = 0; j < 8; j++) bl[j] = bias[n0 + tc * 8 + j];

    #pragma unroll
    for (int i = 0; i < 8; i++) {
        const int m = m0 + tr * 8 + i;    // uniform across the 16-lane group
        float rs = 0.f;
        if (m < MROWS) {
            const float mk = amask[m + m / SM1 + 1];
            float c[8];
            #pragma unroll
            for (int j = 0; j < 8; j++) {
                c[j] = (acc[i][j] + bl[j]) * mk;
                rs += c[j] * c[j];
            }
            float* dst = Cout + (size_t)m * HID + n0 + tc * 8;
            *(float4*)dst       = make_float4(c[0], c[1], c[2], c[3]);
            *(float4*)(dst + 4) = make_float4(c[4], c[5], c[6], c[7]);
        }
        // reduce rs across the 16 tc-lanes (same warp segment) -> deterministic
        #pragma unroll
        for (int o = 8; o; o >>= 1) rs += __shfl_xor_sync(0xffffffffu, rs, o, 16);
        if (tc == 0 && m < MROWS) g_ssq_part[(size_t)m * 8 + bx] = rs;
    }
}

// ---------------------------------------------------------------------------
// Normalize colbert rows: fixed-order sum of the 8 N-tile partials.
// ---------------------------------------------------------------------------
__global__ void colbert_norm_kernel(float* __restrict__ Cout) {
    size_t idx = (size_t)blockIdx.x * blockDim.x + threadIdx.x;  // float4 index
    const size_t total = (size_t)MROWS * (HID / 4);
    if (idx >= total) return;
    int row = (int)(idx >> 8);  // HID/4 == 256
    float ss = 0.f;
    #pragma unroll
    for (int n = 0; n < 8; n++) ss += g_ssq_part[(size_t)row * 8 + n];
    float sc = 1.f / fmaxf(sqrtf(ss), EPSV);
    float4* p = (float4*)Cout + idx;
    float4 v = *p;
    v.x *= sc; v.y *= sc; v.z *= sc; v.w *= sc;
    *p = v;
}

// ---------------------------------------------------------------------------
extern "C" void kernel_launch(void* const* d_in, const int* in_sizes, int n_in,
                              void* d_out, int out_size) {
    const float* hs  = (const float*)d_in[0];   // hidden_state (B,S,H)
    const float* am  = (const float*)d_in[1];   // attention_mask (B,S)
    const void*  ids = d_in[2];                 // input_ids (B,S) i32 or i64
    const float* sW  = (const float*)d_in[3];   // sparse_W (H,1)
    const float* sb  = (const float*)d_in[4];   // sparse_b (1,)
    const float* cW  = (const float*)d_in[5];   // colbert_W (H,H)
    const float* cb  = (const float*)d_in[6];   // colbert_b (H,)

    float* out     = (float*)d_out;
    float* dense   = out;
    float* sparse  = out + OFF_SPARSE;
    float* colbert = out + OFF_COLBERT;

    cudaMemsetAsync(sparse, 0, (size_t)BATCH * VOCAB * sizeof(float), 0);
    detect_i64_kernel<<<1, 256>>>((const unsigned int*)ids);
    dense_kernel<<<BATCH, 256>>>(hs, dense);
    sparse_kernel<<<4096, 256>>>(hs, sW, sb, ids, sparse);

    dim3 ggrid(8, 256);  // 8 N-tiles x 256 M-tiles (covers 32752 rows)
    colbert_gemm_kernel<<<ggrid, 256>>>(hs, cW, cb, am, colbert);
    colbert_norm_kernel<<<MROWS, 256>>>(colbert);
}

// round 3
// speedup vs baseline: 1.9954x; 1.9954x over previous
#include <cuda_runtime.h>
#include <cuda_bf16.h>
#include <stdint.h>

#define BATCH 16
#define SEQ   2048
#define HID   1024
#define VOCAB 250002
#define SM1   2047                 // S-1
#define MROWS (BATCH * SM1)        // 32752 colbert rows
#define MPAD  32768                // padded to multiple of 128
#define EPSV  1e-12f

static const size_t OFF_SPARSE  = (size_t)BATCH * HID;                 // 16384
static const size_t OFF_COLBERT = OFF_SPARSE + (size_t)BATCH * VOCAB;  // 4016416

// ---------------- device scratch (static, no allocs) -----------------------
__device__ float g_ssq_part[(size_t)MROWS * 8];
__device__ int   g_is64;
__device__ __nv_bfloat16 g_Wt_hi[(size_t)HID * HID];   // Wt[n][k] (col-major B)
__device__ __nv_bfloat16 g_Wt_lo[(size_t)HID * HID];
__device__ __nv_bfloat16 g_Ah[(size_t)MPAD * HID];     // A rows (skipping CLS), bf16 hi
__device__ __nv_bfloat16 g_Al[(size_t)MPAD * HID];     // bf16 lo residual

// ---------------- PTX helpers (plain sm_103-safe: sm_80 era) ----------------
__device__ __forceinline__ uint32_t smem_u32(const void* p) {
    uint32_t a;
    asm("{ .reg .u64 t; cvta.to.shared.u64 t, %1; cvt.u32.u64 %0, t; }" : "=r"(a) : "l"(p));
    return a;
}
#define CP16(dst, src) \
    asm volatile("cp.async.cg.shared.global [%0], [%1], 16;" :: "r"(dst), "l"(src))
#define CPCOMMIT() asm volatile("cp.async.commit_group;" ::: "memory")
#define CPWAIT1()  asm volatile("cp.async.wait_group 1;" ::: "memory")
#define CPWAIT0()  asm volatile("cp.async.wait_group 0;" ::: "memory")

#define LDMX4(r, addr)                                                  \
    asm volatile("ldmatrix.sync.aligned.m8n8.x4.shared.b16 {%0,%1,%2,%3}, [%4];" \
        : "=r"((r)[0]), "=r"((r)[1]), "=r"((r)[2]), "=r"((r)[3]) : "r"(addr))

#define MMA_BF16(d, a, b0, b1)                                          \
    asm volatile("mma.sync.aligned.m16n8k16.row.col.f32.bf16.bf16.f32 " \
        "{%0,%1,%2,%3}, {%4,%5,%6,%7}, {%8,%9}, {%0,%1,%2,%3};"         \
        : "+f"((d)[0]), "+f"((d)[1]), "+f"((d)[2]), "+f"((d)[3])        \
        : "r"((a)[0]), "r"((a)[1]), "r"((a)[2]), "r"((a)[3]), "r"(b0), "r"(b1))

// ---------------- GEMM geometry --------------------------------------------
#define BM 128
#define BN 128
#define BK 32
#define SROWB 80                      // padded SMEM row: 40 bf16 = 80 bytes
#define TILEB (128 * SROWB)           // 10240 bytes per operand tile
#define OFFS_AH 0
#define OFFS_AL (1 * TILEB)
#define OFFS_BH (2 * TILEB)
#define OFFS_BL (3 * TILEB)
#define STAGEB  (4 * TILEB)           // 40960
#define SMEMB   (2 * STAGEB)          // 81920

// ---------------------------------------------------------------------------
__global__ void detect_i64_kernel(const unsigned int* __restrict__ w) {
    __shared__ int anynz;
    if (threadIdx.x == 0) anynz = 0;
    __syncthreads();
    int loc = 0;
    for (int i = threadIdx.x; i < BATCH * SEQ / 2; i += blockDim.x)
        loc |= (w[2 * i + 1] != 0u);
    if (loc) atomicOr(&anynz, 1);
    __syncthreads();
    if (threadIdx.x == 0) g_is64 = (anynz == 0);
}

// ---------------------------------------------------------------------------
__global__ void dense_kernel(const float* __restrict__ hs, float* __restrict__ out) {
    int b = blockIdx.x, t = threadIdx.x;
    const float4* x4 = (const float4*)(hs + (size_t)b * SEQ * HID);
    float4 v = x4[t];
    float s = v.x * v.x + v.y * v.y + v.z * v.z + v.w * v.w;
    #pragma unroll
    for (int o = 16; o; o >>= 1) s += __shfl_xor_sync(0xffffffffu, s, o);
    __shared__ float red[8];
    __shared__ float scv;
    if ((t & 31) == 0) red[t >> 5] = s;
    __syncthreads();
    if (t == 0) {
        float a = 0.f;
        #pragma unroll
        for (int i = 0; i < 8; i++) a += red[i];
        scv = 1.f / fmaxf(sqrtf(a), EPSV);
    }
    __syncthreads();
    float sc = scv;
    v.x *= sc; v.y *= sc; v.z *= sc; v.w *= sc;
    ((float4*)(out + (size_t)b * HID))[t] = v;
}

// ---------------------------------------------------------------------------
__global__ void sparse_kernel(const float* __restrict__ hs,
                              const float* __restrict__ sW,
                              const float* __restrict__ sb,
                              const void* __restrict__ ids,
                              float* __restrict__ sparse_out) {
    __shared__ float4 w4[HID / 4];
    for (int i = threadIdx.x; i < HID / 4; i += blockDim.x)
        w4[i] = ((const float4*)sW)[i];
    __syncthreads();

    int gw   = (blockIdx.x * blockDim.x + threadIdx.x) >> 5;
    int lane = threadIdx.x & 31;
    const float4* x4 = (const float4*)(hs + (size_t)gw * HID);
    float s = 0.f;
    #pragma unroll
    for (int i = 0; i < 8; i++) {
        float4 a = x4[lane + i * 32];
        float4 b = w4[lane + i * 32];
        s += a.x * b.x + a.y * b.y + a.z * b.z + a.w * b.w;
    }
    #pragma unroll
    for (int o = 16; o; o >>= 1) s += __shfl_xor_sync(0xffffffffu, s, o);
    if (lane == 0) {
        float tw = s + sb[0];
        if (tw > 0.f) {
            long long id = g_is64 ? ((const long long*)ids)[gw]
                                  : (long long)((const int*)ids)[gw];
            if (id >= 4) {
                int b = gw / SEQ;
                atomicMax((unsigned int*)(sparse_out + (size_t)b * VOCAB + (size_t)id),
                          __float_as_uint(tw));
            }
        }
    }
}

// ---------------------------------------------------------------------------
// W transpose + bf16 hi/lo split: Wt[n][k] = split(W[k][n])
// ---------------------------------------------------------------------------
__global__ void wt_split_kernel(const float* __restrict__ W) {
    __shared__ float tile[32][33];
    int n0 = blockIdx.x * 32, k0 = blockIdx.y * 32;
    int tx = threadIdx.x & 31, ty = threadIdx.x >> 5;   // 32 x 8
    #pragma unroll
    for (int i = ty; i < 32; i += 8)
        tile[i][tx] = W[(size_t)(k0 + i) * HID + n0 + tx];
    __syncthreads();
    #pragma unroll
    for (int i = ty; i < 32; i += 8) {
        float v = tile[tx][i];                 // W[k0+tx][n0+i]
        __nv_bfloat16 h = __float2bfloat16(v);
        size_t idx = (size_t)(n0 + i) * HID + k0 + tx;
        g_Wt_hi[idx] = h;
        g_Wt_lo[idx] = __float2bfloat16(v - __bfloat162float(h));
    }
}

// ---------------------------------------------------------------------------
// A hi/lo split with row remap (skip token 0 per batch); zero-pads to MPAD.
// One float4 per thread. Grid: MPAD blocks x 256 threads.
// ---------------------------------------------------------------------------
__global__ void a_split_kernel(const float* __restrict__ hs) {
    int m = blockIdx.x;
    int t = threadIdx.x;                       // float4 index within row
    size_t didx = ((size_t)m * HID + t * 4) / 4;
    uint2 hz = make_uint2(0, 0), lz = make_uint2(0, 0);
    if (m < MROWS) {
        size_t src = (size_t)(m + m / SM1 + 1) * HID + t * 4;
        float4 v = *(const float4*)(hs + src);
        __nv_bfloat162 h0 = __float22bfloat162_rn(make_float2(v.x, v.y));
        __nv_bfloat162 h1 = __float22bfloat162_rn(make_float2(v.z, v.w));
        __nv_bfloat162 l0 = __float22bfloat162_rn(make_float2(
            v.x - __bfloat162float(h0.x), v.y - __bfloat162float(h0.y)));
        __nv_bfloat162 l1 = __float22bfloat162_rn(make_float2(
            v.z - __bfloat162float(h1.x), v.w - __bfloat162float(h1.y)));
        hz = make_uint2(*(uint32_t*)&h0, *(uint32_t*)&h1);
        lz = make_uint2(*(uint32_t*)&l0, *(uint32_t*)&l1);
    }
    ((uint2*)g_Ah)[didx] = hz;
    ((uint2*)g_Al)[didx] = lz;
}

// ---------------------------------------------------------------------------
// colbert GEMM: bf16 mma.sync 3-term split, 128x128x32 tiles, cp.async x2.
// ---------------------------------------------------------------------------
__global__ __launch_bounds__(256)
void colbert_mma_kernel(const float* __restrict__ bias,
                        const float* __restrict__ amask,
                        float* __restrict__ Cout)
{
    extern __shared__ char sm[];
    const uint32_t smb = smem_u32(sm);
    const int tid = threadIdx.x, wid = tid >> 5, lane = tid & 31;
    const int bx = blockIdx.x;                 // N tile (0..7)
    const int m0 = blockIdx.y * BM;
    const int n0 = bx * BN;
    const int wm = wid & 1, wn = wid >> 1;     // warp grid 2(M) x 4(N)

    const __nv_bfloat16* Ah = g_Ah + (size_t)m0 * HID;
    const __nv_bfloat16* Al = g_Al + (size_t)m0 * HID;
    const __nv_bfloat16* Bh = g_Wt_hi + (size_t)n0 * HID;
    const __nv_bfloat16* Bl = g_Wt_lo + (size_t)n0 * HID;

    // cp.async mapping: 512 16B-chunks per operand tile, 2 per thread
    const int r0c = tid >> 2,       cc0 = (tid & 3);
    const int r1c = (tid + 256) >> 2, cc1 = ((tid + 256) & 3);

    float acc[4][4][4];
    #pragma unroll
    for (int a = 0; a < 4; a++)
        #pragma unroll
        for (int b = 0; b < 4; b++)
            #pragma unroll
            for (int c = 0; c < 4; c++) acc[a][b][c] = 0.f;

    // issue stage 0
    {
        const uint32_t sb = smb;
        uint32_t d0 = sb + r0c * SROWB + cc0 * 16;
        uint32_t d1 = sb + r1c * SROWB + cc1 * 16;
        size_t o0 = (size_t)r0c * HID + cc0 * 8;
        size_t o1 = (size_t)r1c * HID + cc1 * 8;
        CP16(d0 + OFFS_AH, Ah + o0); CP16(d1 + OFFS_AH, Ah + o1);
        CP16(d0 + OFFS_AL, Al + o0); CP16(d1 + OFFS_AL, Al + o1);
        CP16(d0 + OFFS_BH, Bh + o0); CP16(d1 + OFFS_BH, Bh + o1);
        CP16(d0 + OFFS_BL, Bl + o0); CP16(d1 + OFFS_BL, Bl + o1);
        CPCOMMIT();
    }

    // ldmatrix lane offsets (bytes)
    const uint32_t lmo = (uint32_t)((lane & 15) * SROWB + (lane >> 4) * 16);

    const int NITER = HID / BK;    // 32
    for (int c = 0; c < NITER; c++) {
        const int st = c & 1;
        if (c + 1 < NITER) {       // prefetch next stage
            const uint32_t sb = smb + (st ^ 1) * STAGEB;
            const int k0 = (c + 1) * BK;
            uint32_t d0 = sb + r0c * SROWB + cc0 * 16;
            uint32_t d1 = sb + r1c * SROWB + cc1 * 16;
            size_t o0 = (size_t)r0c * HID + k0 + cc0 * 8;
            size_t o1 = (size_t)r1c * HID + k0 + cc1 * 8;
            CP16(d0 + OFFS_AH, Ah + o0); CP16(d1 + OFFS_AH, Ah + o1);
            CP16(d0 + OFFS_AL, Al + o0); CP16(d1 + OFFS_AL, Al + o1);
            CP16(d0 + OFFS_BH, Bh + o0); CP16(d1 + OFFS_BH, Bh + o1);
            CP16(d0 + OFFS_BL, Bl + o0); CP16(d1 + OFFS_BL, Bl + o1);
            CPCOMMIT();
            CPWAIT1();
        } else {
            CPWAIT0();
        }
        __syncthreads();

        const uint32_t sb = smb + st * STAGEB;
        #pragma unroll
        for (int ks = 0; ks < 2; ks++) {
            const uint32_t ko = ks * 32;   // 16 bf16 = 32 bytes
            uint32_t ah[4][4], al[4][4], bh[2][4], bl[2][4];
            #pragma unroll
            for (int mi = 0; mi < 4; mi++) {
                uint32_t ra = sb + (uint32_t)((wm * 64 + mi * 16) * SROWB) + lmo + ko;
                LDMX4(ah[mi], ra + OFFS_AH);
                LDMX4(al[mi], ra + OFFS_AL);
            }
            #pragma unroll
            for (int ni = 0; ni < 2; ni++) {
                uint32_t rb = sb + (uint32_t)((wn * 32 + ni * 16) * SROWB) + lmo + ko;
                LDMX4(bh[ni], rb + OFFS_BH);
                LDMX4(bl[ni], rb + OFFS_BL);
            }
            #pragma unroll
            for (int mi = 0; mi < 4; mi++)
                #pragma unroll
                for (int ni = 0; ni < 2; ni++)
                    #pragma unroll
                    for (int sub = 0; sub < 2; sub++) {
                        const int j = ni * 2 + sub;
                        MMA_BF16(acc[mi][j], ah[mi], bh[ni][sub], bh[ni][sub + 2]);
                        MMA_BF16(acc[mi][j], ah[mi], bl[ni][sub], bl[ni][sub + 2]);
                        MMA_BF16(acc[mi][j], al[mi], bh[ni][sub], bh[ni][sub + 2]);
                    }
        }
        __syncthreads();
    }

    // -------- epilogue: bias + mask, store, deterministic ssq partials ------
    float bj[4][2];
    #pragma unroll
    for (int j = 0; j < 4; j++) {
        int cb = n0 + wn * 32 + j * 8 + (lane & 3) * 2;
        bj[j][0] = bias[cb];
        bj[j][1] = bias[cb + 1];
    }

    float* ssq_sm = (float*)sm;    // [128][4], reuse (post-sync)

    #pragma unroll
    for (int mi = 0; mi < 4; mi++)
        #pragma unroll
        for (int h = 0; h < 2; h++) {
            const int rt = wm * 64 + mi * 16 + h * 8 + (lane >> 2);
            const int m  = m0 + rt;
            const bool mv = m < MROWS;
            const float mk = mv ? amask[m + m / SM1 + 1] : 0.f;
            float s = 0.f;
            #pragma unroll
            for (int j = 0; j < 4; j++) {
                float v0 = (acc[mi][j][h * 2 + 0] + bj[j][0]) * mk;
                float v1 = (acc[mi][j][h * 2 + 1] + bj[j][1]) * mk;
                s += v0 * v0 + v1 * v1;
                if (mv) {
                    int cb = n0 + wn * 32 + j * 8 + (lane & 3) * 2;
                    *(float2*)(Cout + (size_t)m * HID + cb) = make_float2(v0, v1);
                }
            }
            s += __shfl_xor_sync(0xffffffffu, s, 1);
            s += __shfl_xor_sync(0xffffffffu, s, 2);
            if ((lane & 3) == 0) ssq_sm[rt * 4 + wn] = s;
        }
    __syncthreads();
    if (tid < 128) {
        int m = m0 + tid;
        if (m < MROWS) {
            float s = ssq_sm[tid * 4 + 0] + ssq_sm[tid * 4 + 1]
                    + ssq_sm[tid * 4 + 2] + ssq_sm[tid * 4 + 3];
            g_ssq_part[(size_t)m * 8 + bx] = s;
        }
    }
}

// ---------------------------------------------------------------------------
__global__ void colbert_norm_kernel(float* __restrict__ Cout) {
    size_t idx = (size_t)blockIdx.x * blockDim.x + threadIdx.x;
    const size_t total = (size_t)MROWS * (HID / 4);
    if (idx >= total) return;
    int row = (int)(idx >> 8);
    float ss = 0.f;
    #pragma unroll
    for (int n = 0; n < 8; n++) ss += g_ssq_part[(size_t)row * 8 + n];
    float sc = 1.f / fmaxf(sqrtf(ss), EPSV);
    float4* p = (float4*)Cout + idx;
    float4 v = *p;
    v.x *= sc; v.y *= sc; v.z *= sc; v.w *= sc;
    *p = v;
}

// ---------------------------------------------------------------------------
extern "C" void kernel_launch(void* const* d_in, const int* in_sizes, int n_in,
                              void* d_out, int out_size) {
    const float* hs  = (const float*)d_in[0];
    const float* am  = (const float*)d_in[1];
    const void*  ids = d_in[2];
    const float* sW  = (const float*)d_in[3];
    const float* sb  = (const float*)d_in[4];
    const float* cW  = (const float*)d_in[5];
    const float* cb  = (const float*)d_in[6];

    float* out     = (float*)d_out;
    float* dense   = out;
    float* sparse  = out + OFF_SPARSE;
    float* colbert = out + OFF_COLBERT;

    cudaFuncSetAttribute(colbert_mma_kernel,
                         cudaFuncAttributeMaxDynamicSharedMemorySize, SMEMB);

    cudaMemsetAsync(sparse, 0, (size_t)BATCH * VOCAB * sizeof(float), 0);
    detect_i64_kernel<<<1, 256>>>((const unsigned int*)ids);
    dense_kernel<<<BATCH, 256>>>(hs, dense);
    wt_split_kernel<<<dim3(32, 32), 256>>>(cW);
    a_split_kernel<<<MPAD, 256>>>(hs);
    sparse_kernel<<<4096, 256>>>(hs, sW, sb, ids, sparse);

    colbert_mma_kernel<<<dim3(8, 256), 256, SMEMB>>>(cb, am, colbert);
    colbert_norm_kernel<<<MROWS, 256>>>(colbert);
}